// round 14
// baseline (speedup 1.0000x reference)
#include <cuda_runtime.h>
#include <cuda_fp16.h>
#include <math.h>
#include <stdint.h>

// out = ((cos-product head)(x @ Wp^T + bp + theta)) @ Wc^T + bc
// Quantum head closed form (CNOT ring = linear XOR map on basis bits):
//   expz[w] = prod_{j=0..w} cos(ang_j)  (w>=1);  expz[0] = prod_{j=1..7} cos(ang_j)
//
// Single persistent kernel (128 CTAs = one wave, 1 CTA/SM by smem) with
// software grid barriers:
//   Phase A: fp32->fp16 convert (x, Wp, Wc)
//   Phase B: GEMM1 fp16 + quantum-head epilogue -> E
//   Phase C: GEMM2 fp16 + bias -> out
// Tensor path: mma.sync m16n8k16 fp16 (tcgen05 PTX rejected at sm_103 target).
// Error ledger (measured R6-R13): combined fp16 truncation 5.7e-4 < 1e-3 gate.

#define M_DIM 4096
#define N_DIM 768
#define KD    768
#define BM    128
#define BN    192
#define BK    64
#define NITER (KD / BK)        // 12
#define THREADS 256
#define NBLOCKS 128

#define AROWS   BM
#define CPAD    (BN + 4)
#define STAGE_B ((BM + BN) * 128)    // 40960
#define SMEM_SZ (4 * STAGE_B)        // 163840 -> 1 CTA/SM -> single wave

// ---- device scratch (allocation-free rule; zero-initialized) ----
__device__ __half g_A[(size_t)M_DIM * KD];
__device__ __half g_Bp[(size_t)N_DIM * KD];
__device__ __half g_Bc[(size_t)N_DIM * KD];
__device__ __half g_E[(size_t)M_DIM * KD];
__device__ int g_cnt[2];
__device__ volatile int g_gen[2];

// ---- helpers ----
__device__ __forceinline__ uint32_t smem_u32(const void* p) {
    uint32_t a;
    asm("{ .reg .u64 t; cvta.to.shared.u64 t, %1; cvt.u32.u64 %0, t; }" : "=r"(a) : "l"(p));
    return a;
}
__device__ __forceinline__ void cp_async16(uint32_t dst, const void* src) {
    asm volatile("cp.async.cg.shared.global [%0], [%1], 16;" :: "r"(dst), "l"(src));
}
__device__ __forceinline__ void ldsm4(uint32_t* r, uint32_t addr) {
    asm volatile("ldmatrix.sync.aligned.m8n8.x4.shared.b16 {%0,%1,%2,%3}, [%4];"
                 : "=r"(r[0]), "=r"(r[1]), "=r"(r[2]), "=r"(r[3]) : "r"(addr));
}
__device__ __forceinline__ void mma_f16(float* c, const uint32_t* a, uint32_t b0, uint32_t b1) {
    asm volatile(
        "mma.sync.aligned.m16n8k16.row.col.f32.f16.f16.f32 "
        "{%0,%1,%2,%3}, {%4,%5,%6,%7}, {%8,%9}, {%0,%1,%2,%3};"
        : "+f"(c[0]), "+f"(c[1]), "+f"(c[2]), "+f"(c[3])
        : "r"(a[0]), "r"(a[1]), "r"(a[2]), "r"(a[3]), "r"(b0), "r"(b1));
}

// Self-resetting grid barrier. Valid because all NBLOCKS CTAs are
// simultaneously resident (128 CTAs, 1 CTA/SM, 148 SMs).
__device__ __forceinline__ void grid_barrier(int id) {
    __syncthreads();
    if (threadIdx.x == 0) {
        int my = g_gen[id];
        __threadfence();
        int old = atomicAdd(&g_cnt[id], 1);
        if (old == NBLOCKS - 1) {
            g_cnt[id] = 0;          // reset for next replay
            __threadfence();
            g_gen[id] = my + 1;     // release
        } else {
            while (g_gen[id] == my) __nanosleep(64);
        }
        __threadfence();
    }
    __syncthreads();
}

// ---- GEMM phase: C(fp32 acc) = A(fp16) @ B(fp16)^T, K=768 ----
// 128x192 tile, 8 warps 2x4 (64x48), BK=64, 4-stage cp.async,
// ONE __syncthreads per iter, XOR-swizzled 128B smem rows.
template <bool QUANTUM>
__device__ __forceinline__ void gemm_phase(
    char* smem, uint32_t sb, int bm, int bn,
    const __half* __restrict__ A, const __half* __restrict__ B,
    const float* __restrict__ bias, const float* __restrict__ theta,
    __half* __restrict__ E, float* __restrict__ out)
{
    const int tid = threadIdx.x;
    const int l = tid & 31;
    const int wid = tid >> 5;
    const int warp_m = wid & 1;
    const int warp_n = wid >> 1;

    float acc[4][6][4];
#pragma unroll
    for (int mi = 0; mi < 4; mi++)
#pragma unroll
        for (int ni = 0; ni < 6; ni++)
#pragma unroll
            for (int q = 0; q < 4; q++) acc[mi][ni][q] = 0.0f;

    auto load_stage = [&](int s, int k0) {
        uint32_t stage = sb + s * STAGE_B;
#pragma unroll
        for (int i = 0; i < 10; i++) {
            int id = tid + i * THREADS;
            int row = id >> 3;
            int c = id & 7;
            int cs = c ^ (row & 7);
            uint32_t dst = stage + row * 128 + cs * 16;
            const __half* g;
            if (row < AROWS) g = A + (size_t)(bm + row) * KD + k0 + c * 8;
            else             g = B + (size_t)(bn + row - AROWS) * KD + k0 + c * 8;
            cp_async16(dst, g);
        }
    };

    load_stage(0, 0);
    asm volatile("cp.async.commit_group;");
    load_stage(1, BK);
    asm volatile("cp.async.commit_group;");
    load_stage(2, 2 * BK);
    asm volatile("cp.async.commit_group;");

    const int lr = l & 15;
    const int lc = l >> 4;
    const int lx = l & 7;

    for (int kt = 0; kt < NITER; kt++) {
        asm volatile("cp.async.wait_group 2;");
        __syncthreads();

        if (kt + 3 < NITER) load_stage((kt + 3) & 3, (kt + 3) * BK);
        asm volatile("cp.async.commit_group;");

        const uint32_t stage = sb + (kt & 3) * STAGE_B;
#pragma unroll
        for (int ksub = 0; ksub < 4; ksub++) {
            const int cs = (2 * ksub + lc) ^ lx;
            uint32_t a[4][4], b[3][4];
#pragma unroll
            for (int mi = 0; mi < 4; mi++) {
                int row = warp_m * 64 + mi * 16 + lr;
                ldsm4(a[mi], stage + row * 128 + cs * 16);
            }
#pragma unroll
            for (int q = 0; q < 3; q++) {
                int row = AROWS + warp_n * 48 + q * 16 + lr;
                ldsm4(b[q], stage + row * 128 + cs * 16);
            }
#pragma unroll
            for (int mi = 0; mi < 4; mi++)
#pragma unroll
                for (int q = 0; q < 3; q++) {
                    mma_f16(acc[mi][2 * q],     a[mi], b[q][0], b[q][2]);
                    mma_f16(acc[mi][2 * q + 1], a[mi], b[q][1], b[q][3]);
                }
        }
    }
    asm volatile("cp.async.wait_group 0;");
    __syncthreads();

    if (QUANTUM) {
        // stage accums through smem, then closed-form quantum head per 8-col group
        float* Cs = (float*)smem;
#pragma unroll
        for (int mi = 0; mi < 4; mi++)
#pragma unroll
            for (int ni = 0; ni < 6; ni++) {
                int row = warp_m * 64 + mi * 16 + (l >> 2);
                int col = warp_n * 48 + ni * 8 + (l & 3) * 2;
                *(float2*)&Cs[row * CPAD + col]       = make_float2(acc[mi][ni][0], acc[mi][ni][1]);
                *(float2*)&Cs[(row + 8) * CPAD + col] = make_float2(acc[mi][ni][2], acc[mi][ni][3]);
            }
        __syncthreads();

        float th[8];
#pragma unroll
        for (int j = 0; j < 8; j++) th[j] = theta[j];

        // 128 rows x 24 heads = 3072 tasks, 12 per thread
#pragma unroll
        for (int i = 0; i < 12; i++) {
            int g = tid + i * THREADS;
            int r = g / 24;
            int h = g - r * 24;
            int nn = bn + h * 8;
            const float* src = &Cs[r * CPAD + h * 8];
            float cc[8];
#pragma unroll
            for (int j = 0; j < 8; j++)
                cc[j] = __cosf(src[j] + bias[nn + j] + th[j]);
            float o[8];
            float p = cc[0];
#pragma unroll
            for (int j = 1; j < 8; j++) { p *= cc[j]; o[j] = p; }
            float sp = cc[1];
#pragma unroll
            for (int j = 2; j < 8; j++) sp *= cc[j];
            o[0] = sp;
            uint32_t hv[4];
#pragma unroll
            for (int q = 0; q < 4; q++) {
                __half2 hh = __floats2half2_rn(o[2 * q], o[2 * q + 1]);
                hv[q] = *(uint32_t*)&hh;
            }
            *(uint4*)(E + (size_t)(bm + r) * KD + nn) = make_uint4(hv[0], hv[1], hv[2], hv[3]);
        }
    } else {
        // bias add + direct fp32 store
#pragma unroll
        for (int mi = 0; mi < 4; mi++)
#pragma unroll
            for (int ni = 0; ni < 6; ni++) {
                int row = bm + warp_m * 64 + mi * 16 + (l >> 2);
                int col = bn + warp_n * 48 + ni * 8 + (l & 3) * 2;
                float b0 = bias[col], b1 = bias[col + 1];
                *(float2*)&out[(size_t)row * N_DIM + col] =
                    make_float2(acc[mi][ni][0] + b0, acc[mi][ni][1] + b1);
                *(float2*)&out[(size_t)(row + 8) * N_DIM + col] =
                    make_float2(acc[mi][ni][2] + b0, acc[mi][ni][3] + b1);
            }
    }
}

// ---- fused persistent kernel ----
__global__ __launch_bounds__(THREADS)
void fused_kernel(const float* __restrict__ x,
                  const float* __restrict__ wp,
                  const float* __restrict__ wc,
                  const float* __restrict__ bp,
                  const float* __restrict__ theta,
                  const float* __restrict__ bc,
                  float* __restrict__ out)
{
    extern __shared__ char smem[];
    const uint32_t sb = smem_u32(smem);
    const int bm = blockIdx.y * BM;
    const int bn = blockIdx.x * BN;

    // ---- Phase A: fp32 -> fp16 convert (x, wp, wc); 16 floats per task ----
    {
        const int n16x = M_DIM * KD / 16;     // 196608
        const int n16w = N_DIM * KD / 16;     // 36864
        const int total = n16x + 2 * n16w;    // 270336
        int gtid = (blockIdx.y * gridDim.x + blockIdx.x) * THREADS + threadIdx.x;
        for (int i = gtid; i < total; i += NBLOCKS * THREADS) {
            const float* src; __half* dst; int j;
            if (i < n16x)            { src = x;  dst = g_A;  j = i; }
            else if (i < n16x + n16w){ src = wp; dst = g_Bp; j = i - n16x; }
            else                     { src = wc; dst = g_Bc; j = i - n16x - n16w; }
            float4 v0 = ((const float4*)src)[j * 4 + 0];
            float4 v1 = ((const float4*)src)[j * 4 + 1];
            float4 v2 = ((const float4*)src)[j * 4 + 2];
            float4 v3 = ((const float4*)src)[j * 4 + 3];
            __half2 h0 = __floats2half2_rn(v0.x, v0.y);
            __half2 h1 = __floats2half2_rn(v0.z, v0.w);
            __half2 h2 = __floats2half2_rn(v1.x, v1.y);
            __half2 h3 = __floats2half2_rn(v1.z, v1.w);
            __half2 h4 = __floats2half2_rn(v2.x, v2.y);
            __half2 h5 = __floats2half2_rn(v2.z, v2.w);
            __half2 h6 = __floats2half2_rn(v3.x, v3.y);
            __half2 h7 = __floats2half2_rn(v3.z, v3.w);
            ((uint4*)dst)[j * 2 + 0] = make_uint4(*(uint32_t*)&h0, *(uint32_t*)&h1,
                                                  *(uint32_t*)&h2, *(uint32_t*)&h3);
            ((uint4*)dst)[j * 2 + 1] = make_uint4(*(uint32_t*)&h4, *(uint32_t*)&h5,
                                                  *(uint32_t*)&h6, *(uint32_t*)&h7);
        }
    }
    grid_barrier(0);

    // ---- Phase B: GEMM1 + quantum head -> E ----
    gemm_phase<true>(smem, sb, bm, bn, g_A, g_Bp, bp, theta, g_E, nullptr);
    grid_barrier(1);

    // ---- Phase C: GEMM2 + bias -> out ----
    gemm_phase<false>(smem, sb, bm, bn, g_E, g_Bc, bc, nullptr, nullptr, out);
}

extern "C" void kernel_launch(void* const* d_in, const int* in_sizes, int n_in,
                              void* d_out, int out_size)
{
    const float* x      = (const float*)d_in[0];
    const float* W_proj = (const float*)d_in[1];
    const float* b_proj = (const float*)d_in[2];
    const float* theta  = (const float*)d_in[3];
    const float* W_comb = (const float*)d_in[4];
    const float* b_comb = (const float*)d_in[5];
    float* out = (float*)d_out;

    cudaFuncSetAttribute(fused_kernel, cudaFuncAttributeMaxDynamicSharedMemorySize, SMEM_SZ);

    dim3 grid(N_DIM / BN, M_DIM / BM);  // (4, 32) = 128 CTAs, all resident (1/SM)
    fused_kernel<<<grid, THREADS, SMEM_SZ>>>(x, W_proj, W_comb,
                                             b_proj, theta, b_comb, out);
}

// round 15
// speedup vs baseline: 1.1445x; 1.1445x over previous
#include <cuda_runtime.h>
#include <cuda_fp16.h>
#include <math.h>
#include <stdint.h>

// out = ((cos-product head)(x @ Wp^T + bp + theta)) @ Wc^T + bc
// Quantum head closed form (CNOT ring = linear XOR map on basis bits):
//   expz[w] = prod_{j=0..w} cos(ang_j)  (w>=1);  expz[0] = prod_{j=1..7} cos(ang_j)
//
// Tensor path: mma.sync m16n8k16 fp16 (HMMA; tcgen05 PTX rejected at sm_103 target).
// Both GEMMs plain fp16 (K=768), fp32 accumulate. Error 5.7e-4 (measured, stable).
//
// R15: 148-CTA tiling. BM=112 (37 M-tiles x 4 N-tiles = 148 = SM count).
// 112 rows = 7 m-frags, split asymmetrically: warps 0-3 take 4 frags (rows 0-63),
// warps 4-7 take 3 frags (rows 64-111). Warps i and i+4 share SMSP i -> each
// SMSP carries exactly 7 m-frags (balanced). Last M-tile: loads row-clamped,
// stores guarded.

#define M_DIM 4096
#define N_DIM 768
#define KD    768
#define BM    112
#define BN    192
#define BK    64
#define NITER (KD / BK)        // 12
#define THREADS 256
#define M_TILES 37             // 37*112 = 4144 >= 4096

#define AROWS   BM             // 112
#define TROWS   (BM + BN)      // 304
#define STAGE_B (TROWS * 128)  // 38912
#define SMEM_SZ (4 * STAGE_B)  // 155648
#define CPAD    (BN + 4)
#define NCHUNK  (TROWS * 8)    // 2432 16B chunks per stage

// ---- device scratch (allocation-free rule) ----
__device__ __half g_A[(size_t)M_DIM * KD];
__device__ __half g_Bp[(size_t)N_DIM * KD];
__device__ __half g_Bc[(size_t)N_DIM * KD];
__device__ __half g_E[(size_t)M_DIM * KD];

// ---- helpers ----
__device__ __forceinline__ uint32_t smem_u32(const void* p) {
    uint32_t a;
    asm("{ .reg .u64 t; cvta.to.shared.u64 t, %1; cvt.u32.u64 %0, t; }" : "=r"(a) : "l"(p));
    return a;
}
__device__ __forceinline__ void cp_async16(uint32_t dst, const void* src) {
    asm volatile("cp.async.cg.shared.global [%0], [%1], 16;" :: "r"(dst), "l"(src));
}
__device__ __forceinline__ void ldsm4(uint32_t* r, uint32_t addr) {
    asm volatile("ldmatrix.sync.aligned.m8n8.x4.shared.b16 {%0,%1,%2,%3}, [%4];"
                 : "=r"(r[0]), "=r"(r[1]), "=r"(r[2]), "=r"(r[3]) : "r"(addr));
}
__device__ __forceinline__ void mma_f16(float* c, const uint32_t* a, uint32_t b0, uint32_t b1) {
    asm volatile(
        "mma.sync.aligned.m16n8k16.row.col.f32.f16.f16.f32 "
        "{%0,%1,%2,%3}, {%4,%5,%6,%7}, {%8,%9}, {%0,%1,%2,%3};"
        : "+f"(c[0]), "+f"(c[1]), "+f"(c[2]), "+f"(c[3])
        : "r"(a[0]), "r"(a[1]), "r"(a[2]), "r"(a[3]), "r"(b0), "r"(b1));
}

// ---- fp32 -> fp16 convert (x, wp, wc); 16 floats per thread ----
__global__ void conv_kernel(const float* __restrict__ x,
                            const float* __restrict__ wp,
                            const float* __restrict__ wc) {
    const int n16x = M_DIM * KD / 16;
    const int n16w = N_DIM * KD / 16;
    int i = blockIdx.x * blockDim.x + threadIdx.x;
    const float* src; __half* dst; int j;
    if (i < n16x)               { src = x;  dst = g_A;  j = i; }
    else if (i < n16x + n16w)   { src = wp; dst = g_Bp; j = i - n16x; }
    else if (i < n16x + 2*n16w) { src = wc; dst = g_Bc; j = i - n16x - n16w; }
    else return;
    float4 v0 = ((const float4*)src)[j * 4 + 0];
    float4 v1 = ((const float4*)src)[j * 4 + 1];
    float4 v2 = ((const float4*)src)[j * 4 + 2];
    float4 v3 = ((const float4*)src)[j * 4 + 3];
    __half2 h0 = __floats2half2_rn(v0.x, v0.y);
    __half2 h1 = __floats2half2_rn(v0.z, v0.w);
    __half2 h2 = __floats2half2_rn(v1.x, v1.y);
    __half2 h3 = __floats2half2_rn(v1.z, v1.w);
    __half2 h4 = __floats2half2_rn(v2.x, v2.y);
    __half2 h5 = __floats2half2_rn(v2.z, v2.w);
    __half2 h6 = __floats2half2_rn(v3.x, v3.y);
    __half2 h7 = __floats2half2_rn(v3.z, v3.w);
    ((uint4*)dst)[j * 2 + 0] = make_uint4(*(uint32_t*)&h0, *(uint32_t*)&h1,
                                          *(uint32_t*)&h2, *(uint32_t*)&h3);
    ((uint4*)dst)[j * 2 + 1] = make_uint4(*(uint32_t*)&h4, *(uint32_t*)&h5,
                                          *(uint32_t*)&h6, *(uint32_t*)&h7);
}

// ---- GEMM body, templated on m-frag count / base row within the CTA tile ----
template <bool QUANTUM, int MFR, int MBASE>
__device__ __forceinline__ void gemm_body(
    char* smem, uint32_t sb, int bm, int bn,
    const __half* __restrict__ A, const __half* __restrict__ B,
    const float* __restrict__ bias, const float* __restrict__ theta,
    __half* __restrict__ E, float* __restrict__ out)
{
    const int tid = threadIdx.x;
    const int l = tid & 31;
    const int wid = tid >> 5;
    const int warp_n = wid & 3;    // 4 x 48 cols

    float acc[MFR][6][4];
#pragma unroll
    for (int mi = 0; mi < MFR; mi++)
#pragma unroll
        for (int ni = 0; ni < 6; ni++)
#pragma unroll
            for (int q = 0; q < 4; q++) acc[mi][ni][q] = 0.0f;

    // cooperative load: 2432 16B chunks/stage, 10 per thread (guarded).
    // A rows clamped to M_DIM-1 for the partial last tile.
    auto load_stage = [&](int s, int k0) {
        uint32_t stage = sb + s * STAGE_B;
#pragma unroll
        for (int i = 0; i < 10; i++) {
            int id = tid + i * THREADS;
            if (id < NCHUNK) {
                int row = id >> 3;
                int c = id & 7;
                uint32_t dst = stage + row * 128 + (c ^ (row & 7)) * 16;
                const __half* g;
                if (row < AROWS) {
                    int gr = bm + row;
                    if (gr > M_DIM - 1) gr = M_DIM - 1;
                    g = A + (size_t)gr * KD + k0 + c * 8;
                } else {
                    g = B + (size_t)(bn + row - AROWS) * KD + k0 + c * 8;
                }
                cp_async16(dst, g);
            }
        }
    };

    load_stage(0, 0);
    asm volatile("cp.async.commit_group;");
    load_stage(1, BK);
    asm volatile("cp.async.commit_group;");
    load_stage(2, 2 * BK);
    asm volatile("cp.async.commit_group;");

    const int lr = l & 15;
    const int lc = l >> 4;
    const int lx = l & 7;

    for (int kt = 0; kt < NITER; kt++) {
        asm volatile("cp.async.wait_group 2;");
        __syncthreads();

        if (kt + 3 < NITER) load_stage((kt + 3) & 3, (kt + 3) * BK);
        asm volatile("cp.async.commit_group;");

        const uint32_t stage = sb + (kt & 3) * STAGE_B;
#pragma unroll
        for (int ksub = 0; ksub < 4; ksub++) {
            const int cs = (2 * ksub + lc) ^ lx;
            uint32_t a[MFR][4], b[3][4];
#pragma unroll
            for (int mi = 0; mi < MFR; mi++) {
                int row = MBASE + mi * 16 + lr;
                ldsm4(a[mi], stage + row * 128 + cs * 16);
            }
#pragma unroll
            for (int q = 0; q < 3; q++) {
                int row = AROWS + warp_n * 48 + q * 16 + lr;
                ldsm4(b[q], stage + row * 128 + cs * 16);
            }
#pragma unroll
            for (int mi = 0; mi < MFR; mi++)
#pragma unroll
                for (int q = 0; q < 3; q++) {
                    mma_f16(acc[mi][2 * q],     a[mi], b[q][0], b[q][2]);
                    mma_f16(acc[mi][2 * q + 1], a[mi], b[q][1], b[q][3]);
                }
        }
    }
    asm volatile("cp.async.wait_group 0;");
    __syncthreads();

    if (QUANTUM) {
        // stage accums through smem, then closed-form quantum head per 8-col group
        float* Cs = (float*)smem;
#pragma unroll
        for (int mi = 0; mi < MFR; mi++)
#pragma unroll
            for (int ni = 0; ni < 6; ni++) {
                int row = MBASE + mi * 16 + (l >> 2);
                int col = warp_n * 48 + ni * 8 + (l & 3) * 2;
                *(float2*)&Cs[row * CPAD + col]       = make_float2(acc[mi][ni][0], acc[mi][ni][1]);
                *(float2*)&Cs[(row + 8) * CPAD + col] = make_float2(acc[mi][ni][2], acc[mi][ni][3]);
            }
        __syncthreads();

        float th[8];
#pragma unroll
        for (int j = 0; j < 8; j++) th[j] = theta[j];

        // 112 rows x 24 heads = 2688 tasks, 11 per thread (guarded)
#pragma unroll
        for (int i = 0; i < 11; i++) {
            int g = tid + i * THREADS;
            if (g < BM * 24) {
                int r = g / 24;
                int h = g - r * 24;
                if (bm + r < M_DIM) {
                    int nn = bn + h * 8;
                    const float* src = &Cs[r * CPAD + h * 8];
                    float cc[8];
#pragma unroll
                    for (int j = 0; j < 8; j++)
                        cc[j] = __cosf(src[j] + bias[nn + j] + th[j]);
                    float o[8];
                    float p = cc[0];
#pragma unroll
                    for (int j = 1; j < 8; j++) { p *= cc[j]; o[j] = p; }
                    float sp = cc[1];
#pragma unroll
                    for (int j = 2; j < 8; j++) sp *= cc[j];
                    o[0] = sp;
                    uint32_t hv[4];
#pragma unroll
                    for (int q = 0; q < 4; q++) {
                        __half2 hh = __floats2half2_rn(o[2 * q], o[2 * q + 1]);
                        hv[q] = *(uint32_t*)&hh;
                    }
                    *(uint4*)(E + (size_t)(bm + r) * KD + nn) =
                        make_uint4(hv[0], hv[1], hv[2], hv[3]);
                }
            }
        }
    } else {
        // bias add + direct fp32 store (row-guarded)
#pragma unroll
        for (int mi = 0; mi < MFR; mi++)
#pragma unroll
            for (int ni = 0; ni < 6; ni++) {
                int row = bm + MBASE + mi * 16 + (l >> 2);
                int col = bn + warp_n * 48 + ni * 8 + (l & 3) * 2;
                float b0 = bias[col], b1 = bias[col + 1];
                if (row < M_DIM)
                    *(float2*)&out[(size_t)row * N_DIM + col] =
                        make_float2(acc[mi][ni][0] + b0, acc[mi][ni][1] + b1);
                if (row + 8 < M_DIM)
                    *(float2*)&out[(size_t)(row + 8) * N_DIM + col] =
                        make_float2(acc[mi][ni][2] + b0, acc[mi][ni][3] + b1);
            }
    }
}

template <bool QUANTUM>
__global__ __launch_bounds__(THREADS)
void mma_gemm(const __half* __restrict__ A,
              const __half* __restrict__ B,
              const float* __restrict__ bias,
              const float* __restrict__ theta,
              __half* __restrict__ E,
              float* __restrict__ out)
{
    extern __shared__ char smem[];
    const uint32_t sb = smem_u32(smem);
    const int bm = blockIdx.y * BM;
    const int bn = blockIdx.x * BN;
    // Warps i and i+4 share SMSP i%4: 4+3 = 7 m-frags per SMSP (balanced).
    if ((threadIdx.x >> 5) < 4)
        gemm_body<QUANTUM, 4, 0 >(smem, sb, bm, bn, A, B, bias, theta, E, out);
    else
        gemm_body<QUANTUM, 3, 64>(smem, sb, bm, bn, A, B, bias, theta, E, out);
}

extern "C" void kernel_launch(void* const* d_in, const int* in_sizes, int n_in,
                              void* d_out, int out_size)
{
    const float* x      = (const float*)d_in[0];
    const float* W_proj = (const float*)d_in[1];
    const float* b_proj = (const float*)d_in[2];
    const float* theta  = (const float*)d_in[3];
    const float* W_comb = (const float*)d_in[4];
    const float* b_comb = (const float*)d_in[5];
    float* out = (float*)d_out;

    cudaFuncSetAttribute(mma_gemm<true>,  cudaFuncAttributeMaxDynamicSharedMemorySize, SMEM_SZ);
    cudaFuncSetAttribute(mma_gemm<false>, cudaFuncAttributeMaxDynamicSharedMemorySize, SMEM_SZ);

    __half *A, *Bp, *Bc, *E;
    cudaGetSymbolAddress((void**)&A,  g_A);
    cudaGetSymbolAddress((void**)&Bp, g_Bp);
    cudaGetSymbolAddress((void**)&Bc, g_Bc);
    cudaGetSymbolAddress((void**)&E,  g_E);

    const int total16 = M_DIM * KD / 16 + 2 * (N_DIM * KD / 16);
    conv_kernel<<<(total16 + 255) / 256, 256>>>(x, W_proj, W_comb);

    dim3 grid(N_DIM / BN, M_TILES);  // (4, 37) = 148 CTAs = SM count
    mma_gemm<true><<<grid, THREADS, SMEM_SZ>>>(A, Bp, b_proj, theta, E, nullptr);
    mma_gemm<false><<<grid, THREADS, SMEM_SZ>>>(E, Bc, b_comb, nullptr, nullptr, out);
}